// round 13
// baseline (speedup 1.0000x reference)
#include <cuda_runtime.h>
#include <cuda_fp16.h>
#include <cstdint>

#define NN      50000
#define NE      800000
#define NMSG    200
#define KP      208           // padded k (13 tiles of 16); A' fp32 & B fp16 row stride
#define TSTR    32            // Tagg row stride (floats)
#define W2KP    216           // Wm2T shared k-stride (halves), bank-clean
#define HSTR    24            // h-tile row stride (halves) = 48B, bank-clean
#define CSTR    36            // C staging row stride (floats)

// ---------------------------------------------------------------------------
// Static device scratch
// ---------------------------------------------------------------------------
__device__ __align__(16) float  g_x0[NN * 30];
__device__ __align__(16) float  g_x1[NN * 30];
__device__ __align__(16) float  g_A [NN * KP];    // A' = (x@Wm1a + bm1) * bs, fp32
__device__ __align__(16) __half g_Bh[NN * KP];    // B  = (x@Wm1b) * bs, fp16
__device__ __align__(16) float  g_T [NN * TSTR];
__device__ int g_is64;
__device__ int g_cnt[NN];
__device__ int g_ofs[NN];
__device__ int g_bsum[64];
__device__ int g_xmaxi[8];     // [0..3]: per-layer max(relu(x)); [7]: const 256.0f
__device__ int g_ssrc[NE];
__device__ int g_sdst[NE];
__device__ __align__(8) float2 g_sw[NE];

// ---------------------------------------------------------------------------
// mma.m16n8k16 f16 x f16 -> f32
// ---------------------------------------------------------------------------
__device__ __forceinline__ void mma16816(float* c,
                                         unsigned a0, unsigned a1, unsigned a2, unsigned a3,
                                         unsigned b0, unsigned b1) {
    asm volatile(
        "mma.sync.aligned.m16n8k16.row.col.f32.f16.f16.f32 "
        "{%0,%1,%2,%3}, {%4,%5,%6,%7}, {%8,%9}, {%0,%1,%2,%3};"
        : "+f"(c[0]), "+f"(c[1]), "+f"(c[2]), "+f"(c[3])
        : "r"(a0), "r"(a1), "r"(a2), "r"(a3), "r"(b0), "r"(b1));
}

// ---------------------------------------------------------------------------
// Edge dtype detection
// ---------------------------------------------------------------------------
__global__ void detect_edges_kernel(const long long* __restrict__ e64) {
    if (threadIdx.x == 0 && blockIdx.x == 0) {
        int ok = 1;
        for (int i = 0; i < 16; i++) {
            long long v = e64[i];
            if (v < 0 || v >= NN) ok = 0;
        }
        g_is64 = ok;
    }
}
__device__ __forceinline__ int load_idx(const void* edges, long long pos, bool is64) {
    if (is64) return (int)((const long long*)edges)[pos];
    return ((const int*)edges)[pos];
}

// ---------------------------------------------------------------------------
// Counting sort by dst (parallel scan)
// ---------------------------------------------------------------------------
__global__ void zero_hist_kernel(int N) {
    int i = blockIdx.x * blockDim.x + threadIdx.x;
    if (i < N) g_cnt[i] = 0;
    if (i < 8) g_xmaxi[i] = (i == 7) ? 0x43800000 : 0;   // slot 7 = 256.0f (bs=1)
}
__global__ void hist_kernel(const void* __restrict__ edges, int E) {
    int e = blockIdx.x * blockDim.x + threadIdx.x;
    if (e >= E) return;
    bool is64 = (g_is64 != 0);
    atomicAdd(&g_cnt[load_idx(edges, (long long)E + e, is64)], 1);
}
__global__ void scan1_kernel(int N) {
    __shared__ int s[1024];
    int i = blockIdx.x * 1024 + threadIdx.x;
    int v = (i < N) ? g_cnt[i] : 0;
    s[threadIdx.x] = v;
    __syncthreads();
    for (int off = 1; off < 1024; off <<= 1) {
        int t = (threadIdx.x >= (unsigned)off) ? s[threadIdx.x - off] : 0;
        __syncthreads();
        s[threadIdx.x] += t;
        __syncthreads();
    }
    if (i < N) g_ofs[i] = s[threadIdx.x] - v;
    if (threadIdx.x == 1023) g_bsum[blockIdx.x] = s[1023];
}
__global__ void scan2_kernel(int nb) {
    if (threadIdx.x == 0 && blockIdx.x == 0) {
        int acc = 0;
        for (int b = 0; b < nb; b++) { int t = g_bsum[b]; g_bsum[b] = acc; acc += t; }
    }
}
__global__ void scan3_kernel(int N) {
    int i = blockIdx.x * 1024 + threadIdx.x;
    if (i < N) g_ofs[i] += g_bsum[blockIdx.x];
}
__global__ void scatter_kernel(const void* __restrict__ edges,
                               const float* __restrict__ ea, int E) {
    int e = blockIdx.x * blockDim.x + threadIdx.x;
    if (e >= E) return;
    bool is64 = (g_is64 != 0);
    int src = load_idx(edges, e, is64);
    int dst = load_idx(edges, (long long)E + e, is64);
    int p = atomicAdd(&g_ofs[dst], 1);
    g_ssrc[p] = src;
    g_sdst[p] = dst;
    g_sw[p]   = ((const float2*)ea)[e];
}

// ---------------------------------------------------------------------------
// Per-node precompute, vectorized (4 k's per thread), PRE-SCALED by bs:
//   A'[n,k] = (relu?(x)·Wm1[0:C,k] + bm1[k]) * bs   (fp32)
//   B [n,k] = (relu?(x)·Wm1[C:2C,k]) * bs           (fp16)
// k >= 200 zero-padded. Also zeroes Tagg.
// ---------------------------------------------------------------------------
template <int C_IN, bool RELU_IN>
__global__ void precomp_ab_kernel(const float* __restrict__ x,
                                  const float* __restrict__ Wm1,
                                  const float* __restrict__ bm1,
                                  float* __restrict__ Ap,
                                  __half* __restrict__ Bh,
                                  const int* __restrict__ xmaxi,
                                  float* __restrict__ Tagg,
                                  int N) {
    int idx = blockIdx.x * blockDim.x + threadIdx.x;
    if (idx < N * TSTR) Tagg[idx] = 0.f;
    if (idx >= N * (KP / 4)) return;
    int n  = idx / (KP / 4);
    int kq = idx - n * (KP / 4);

    if (kq >= NMSG / 4) {   // pad region k in [200,208)
        ((float4*)(Ap + (size_t)n * KP))[kq] = make_float4(0.f, 0.f, 0.f, 0.f);
        __half2 z = __floats2half2_rn(0.f, 0.f);
        __half2* bp = (__half2*)(Bh + (size_t)n * KP + kq * 4);
        bp[0] = z; bp[1] = z;
        return;
    }

    float xmax = __int_as_float(*xmaxi);
    float bs = (xmax > 0.f) ? 256.f / xmax : 1.f;

    float4 a = ((const float4*)bm1)[kq];
    float4 b = make_float4(0.f, 0.f, 0.f, 0.f);
#pragma unroll
    for (int c = 0; c < C_IN; c++) {
        float xv = x[(size_t)n * C_IN + c];
        if (RELU_IN) xv = fmaxf(xv, 0.f);
        float4 wa = ((const float4*)(Wm1 + c * NMSG))[kq];
        float4 wb = ((const float4*)(Wm1 + (C_IN + c) * NMSG))[kq];
        a.x = fmaf(xv, wa.x, a.x); a.y = fmaf(xv, wa.y, a.y);
        a.z = fmaf(xv, wa.z, a.z); a.w = fmaf(xv, wa.w, a.w);
        b.x = fmaf(xv, wb.x, b.x); b.y = fmaf(xv, wb.y, b.y);
        b.z = fmaf(xv, wb.z, b.z); b.w = fmaf(xv, wb.w, b.w);
    }
    a.x *= bs; a.y *= bs; a.z *= bs; a.w *= bs;
    ((float4*)(Ap + (size_t)n * KP))[kq] = a;
    __half2 b01 = __floats2half2_rn(b.x * bs, b.y * bs);
    __half2 b23 = __floats2half2_rn(b.z * bs, b.w * bs);
    __half2* bp = (__half2*)(Bh + (size_t)n * KP + kq * 4);
    bp[0] = b01; bp[1] = b23;
}

// ---------------------------------------------------------------------------
// Node finish: out = b1 + deg*b2 + x@W1 + Tagg@W2; also records max(relu(out))
// ---------------------------------------------------------------------------
template <int C_IN, int C_OUT, bool RELU_IN>
__global__ void node_finish_kernel(const float* __restrict__ x,
                                   const float* __restrict__ W1,
                                   const float* __restrict__ b1,
                                   const float* __restrict__ W2,
                                   const float* __restrict__ b2,
                                   const float* __restrict__ Tagg,
                                   const int* __restrict__ cnt,
                                   float* __restrict__ out,
                                   int* __restrict__ xmax_out,   // nullable
                                   int N) {
    int idx = blockIdx.x * blockDim.x + threadIdx.x;
    float v = 0.f;
    bool inb = (idx < N * C_OUT);
    if (inb) {
        int n  = idx / C_OUT;
        int co = idx - n * C_OUT;
        v = b1[co] + (float)cnt[n] * b2[co];
#pragma unroll
        for (int c = 0; c < C_IN; c++) {
            float xv = x[(size_t)n * C_IN + c];
            if (RELU_IN) xv = fmaxf(xv, 0.f);
            v = fmaf(xv, W1[c * C_OUT + co], v);
            v = fmaf(Tagg[(size_t)n * TSTR + c], W2[c * C_OUT + co], v);
        }
        out[idx] = v;
    }
    if (xmax_out != nullptr) {
        float lv = inb ? fmaxf(v, 0.f) : 0.f;
#pragma unroll
        for (int off = 16; off > 0; off >>= 1)
            lv = fmaxf(lv, __shfl_xor_sync(0xffffffffu, lv, off));
        __shared__ float wmax[8];
        int lane = threadIdx.x & 31, warp = threadIdx.x >> 5;
        if (lane == 0) wmax[warp] = lv;
        __syncthreads();
        if (threadIdx.x == 0) {
            float bm = wmax[0];
#pragma unroll
            for (int i = 1; i < 8; i++) bm = fmaxf(bm, wmax[i]);
            atomicMax(xmax_out, __float_as_int(bm));
        }
    }
}

// ---------------------------------------------------------------------------
// Edge kernel — TENSOR CORE GEMV, split-precision, B prefetch pipeline.
// NT = number of 8-wide n tiles (4 for C_IN=30, 1 for C_IN=1).
// ---------------------------------------------------------------------------
#define SM_WE_B    0
#define SM_W2H_B   (416 * 4)                       // 1664
#define SM_W2L_B   (SM_W2H_B + 32 * W2KP * 2)      // 15488
#define SM_BM2_B   (SM_W2L_B + 32 * W2KP * 2)      // 29312
#define SM_WARP_B  (SM_BM2_B + 128)                // 29440
#define SM_TOTAL_B (SM_WARP_B + 8 * 32 * CSTR * 4) // 66304

template <int C_IN, bool RELU_IN, int NT>
__global__ void __launch_bounds__(256)
edge_mma_kernel(const int* __restrict__ srcArr,
                const int* __restrict__ dstArr,
                const float2* __restrict__ wArr,
                const float* __restrict__ x,
                const float* __restrict__ Ap,
                const __half* __restrict__ Bh,
                const float* __restrict__ Wm1,
                const float* __restrict__ Wm2,
                const float* __restrict__ bm2,
                const int* __restrict__ xmaxi,
                float* __restrict__ Tagg,
                int E) {
    extern __shared__ char smem[];
    float*  sWE  = (float*)(smem + SM_WE_B);
    __half* sW2H = (__half*)(smem + SM_W2H_B);
    __half* sW2L = (__half*)(smem + SM_W2L_B);
    float*  sbm2 = (float*)(smem + SM_BM2_B);

    const int tid = threadIdx.x;
    for (int i = tid; i < 2 * KP; i += 256) {
        int row = i / KP, k = i - row * KP;
        sWE[i] = (k < NMSG) ? Wm1[2 * C_IN * NMSG + row * NMSG + k] : 0.f;
    }
    for (int i = tid; i < 32 * W2KP; i += 256) {
        int n = i / W2KP, k = i - n * W2KP;
        float v = (n < C_IN && k < NMSG) ? Wm2[k * C_IN + n] : 0.f;
        __half hi = __float2half_rn(v);
        sW2H[i] = hi;
        sW2L[i] = __float2half_rn(v - __half2float(hi));
    }
    if (tid < 32) sbm2[tid] = (tid < C_IN) ? bm2[tid] : 0.f;
    __syncthreads();

    const int lane = tid & 31;
    const int warp = tid >> 5;
    const int gq   = lane >> 2;
    const int tg   = lane & 3;
    float*  wb   = (float*)(smem + SM_WARP_B) + warp * (32 * CSTR);
    __half* htH  = (__half*)wb;
    __half* htL  = htH + 32 * HSTR;

    const float xmax   = __int_as_float(*xmaxi);
    const float inv_bs = (xmax > 0.f) ? xmax * (1.f / 256.f) : 1.f;
    const float bs     = (xmax > 0.f) ? 256.f / xmax : 1.f;

    const int e = blockIdx.x * 256 + warp * 32 + lane;
    const bool valid = (e < E);
    int src = 0, dstL = 0, key = -1;
    float2 w = make_float2(0.f, 0.f);
    if (valid) {
        src  = srcArr[e];
        dstL = dstArr[e];
        key  = dstL;
        w    = wArr[e];
    }
    const float wxs = w.x * bs;
    const float wys = w.y * bs;

    const float* Arow = Ap + (size_t)dstL * KP;
    const uint4* B8   = (const uint4*)(Bh + (size_t)src * KP);

    float c[2 * NT][4];
#pragma unroll
    for (int i = 0; i < 2 * NT; i++)
#pragma unroll
        for (int j = 0; j < 4; j++) c[i][j] = 0.f;

    // B prefetch pipeline (src is random -> L2 latency; hide behind compute)
    uint4 pb0 = B8[0];
    uint4 pb1 = B8[1];

#pragma unroll 1
    for (int kt = 0; kt < KP / 16; kt++) {        // 13 tiles
        const int k0 = kt * 16;
        uint4 cb0 = pb0, cb1 = pb1;
        if (kt + 1 < KP / 16) {
            pb0 = B8[(kt + 1) * 2];
            pb1 = B8[(kt + 1) * 2 + 1];
        }

        __align__(16) __half2 hhH[8];
        __align__(16) __half2 hhL[8];
#pragma unroll
        for (int hc = 0; hc < 2; hc++) {
            const int kk = k0 + hc * 8;
            float4 a0 = ((const float4*)(Arow + kk))[0];
            float4 a1 = ((const float4*)(Arow + kk))[1];
            uint4  bv = (hc == 0) ? cb0 : cb1;
            float4 u00 = ((const float4*)(sWE + kk))[0];
            float4 u01 = ((const float4*)(sWE + kk))[1];
            float4 u10 = ((const float4*)(sWE + KP + kk))[0];
            float4 u11 = ((const float4*)(sWE + KP + kk))[1];
            float2 b0 = __half22float2(*(const __half2*)&bv.x);
            float2 b1 = __half22float2(*(const __half2*)&bv.y);
            float2 b2 = __half22float2(*(const __half2*)&bv.z);
            float2 b3 = __half22float2(*(const __half2*)&bv.w);
            float h[8];
            h[0] = fmaxf(fmaf(wxs, u00.x, fmaf(wys, u10.x, a0.x + b0.x)), 0.f);
            h[1] = fmaxf(fmaf(wxs, u00.y, fmaf(wys, u10.y, a0.y + b0.y)), 0.f);
            h[2] = fmaxf(fmaf(wxs, u00.z, fmaf(wys, u10.z, a0.z + b1.x)), 0.f);
            h[3] = fmaxf(fmaf(wxs, u00.w, fmaf(wys, u10.w, a0.w + b1.y)), 0.f);
            h[4] = fmaxf(fmaf(wxs, u01.x, fmaf(wys, u11.x, a1.x + b2.x)), 0.f);
            h[5] = fmaxf(fmaf(wxs, u01.y, fmaf(wys, u11.y, a1.y + b2.y)), 0.f);
            h[6] = fmaxf(fmaf(wxs, u01.z, fmaf(wys, u11.z, a1.z + b3.x)), 0.f);
            h[7] = fmaxf(fmaf(wxs, u01.w, fmaf(wys, u11.w, a1.w + b3.y)), 0.f);
#pragma unroll
            for (int p = 0; p < 4; p++) {
                __half2 hi = __floats2half2_rn(h[2 * p], h[2 * p + 1]);
                float2 hif = __half22float2(hi);
                __half2 lo = __floats2half2_rn(h[2 * p] - hif.x, h[2 * p + 1] - hif.y);
                hhH[hc * 4 + p] = hi;
                hhL[hc * 4 + p] = lo;
            }
        }
        {
            uint4* hwH = (uint4*)(htH + lane * HSTR);
            hwH[0] = *(const uint4*)&hhH[0];
            hwH[1] = *(const uint4*)&hhH[4];
            uint4* hwL = (uint4*)(htL + lane * HSTR);
            hwL[0] = *(const uint4*)&hhL[0];
            hwL[1] = *(const uint4*)&hhL[4];
        }
        __syncwarp();

        unsigned bfH[NT][2], bfL[NT][2];
#pragma unroll
        for (int nt = 0; nt < NT; nt++) {
            const __half* wpH = sW2H + (nt * 8 + gq) * W2KP + k0 + 2 * tg;
            bfH[nt][0] = *(const unsigned*)wpH;
            bfH[nt][1] = *(const unsigned*)(wpH + 8);
            const __half* wpL = sW2L + (nt * 8 + gq) * W2KP + k0 + 2 * tg;
            bfL[nt][0] = *(const unsigned*)wpL;
            bfL[nt][1] = *(const unsigned*)(wpL + 8);
        }
#pragma unroll
        for (int mt = 0; mt < 2; mt++) {
            const __half* hbH = htH + mt * 16 * HSTR;
            unsigned aH0 = *(const unsigned*)(hbH + gq * HSTR + 2 * tg);
            unsigned aH1 = *(const unsigned*)(hbH + (gq + 8) * HSTR + 2 * tg);
            unsigned aH2 = *(const unsigned*)(hbH + gq * HSTR + 2 * tg + 8);
            unsigned aH3 = *(const unsigned*)(hbH + (gq + 8) * HSTR + 2 * tg + 8);
            const __half* hbL = htL + mt * 16 * HSTR;
            unsigned aL0 = *(const unsigned*)(hbL + gq * HSTR + 2 * tg);
            unsigned aL1 = *(const unsigned*)(hbL + (gq + 8) * HSTR + 2 * tg);
            unsigned aL2 = *(const unsigned*)(hbL + gq * HSTR + 2 * tg + 8);
            unsigned aL3 = *(const unsigned*)(hbL + (gq + 8) * HSTR + 2 * tg + 8);
#pragma unroll
            for (int nt = 0; nt < NT; nt++) {
                mma16816(c[mt * NT + nt], aH0, aH1, aH2, aH3, bfH[nt][0], bfH[nt][1]);
                mma16816(c[mt * NT + nt], aH0, aH1, aH2, aH3, bfL[nt][0], bfL[nt][1]);
                mma16816(c[mt * NT + nt], aL0, aL1, aL2, aL3, bfH[nt][0], bfH[nt][1]);
            }
        }
        __syncwarp();
    }

    // Stage C frags to smem: row = edge-in-warp, col = n
#pragma unroll
    for (int mt = 0; mt < 2; mt++)
#pragma unroll
        for (int nt = 0; nt < NT; nt++) {
            float* p = wb + (mt * 16 + gq) * CSTR + nt * 8 + 2 * tg;
            p[0] = c[mt * NT + nt][0];
            p[1] = c[mt * NT + nt][1];
            p[8 * CSTR + 0] = c[mt * NT + nt][2];
            p[8 * CSTR + 1] = c[mt * NT + nt][3];
        }
    __syncwarp();

    // Per-edge m, t, segmented scan, tail atomics
    float t[C_IN];
    {
        const float* mrow = wb + lane * CSTR;
        if constexpr (C_IN == 1) {
            float xi = x[dstL], xj = x[src];
            if (RELU_IN) { xi = fmaxf(xi, 0.f); xj = fmaxf(xj, 0.f); }
            t[0] = fmaf(mrow[0], inv_bs, sbm2[0]) * (xi - xj);
        } else {
            const float2* xd2 = (const float2*)(x + (size_t)dstL * C_IN);
            const float2* xs2 = (const float2*)(x + (size_t)src  * C_IN);
#pragma unroll
            for (int p = 0; p < C_IN / 2; p++) {
                float2 xi = xd2[p];
                float2 xj = xs2[p];
                if (RELU_IN) {
                    xi.x = fmaxf(xi.x, 0.f); xi.y = fmaxf(xi.y, 0.f);
                    xj.x = fmaxf(xj.x, 0.f); xj.y = fmaxf(xj.y, 0.f);
                }
                t[2 * p]     = fmaf(mrow[2 * p],     inv_bs, sbm2[2 * p])     * (xi.x - xj.x);
                t[2 * p + 1] = fmaf(mrow[2 * p + 1], inv_bs, sbm2[2 * p + 1]) * (xi.y - xj.y);
            }
        }
        if (!valid) {
#pragma unroll
            for (int cc = 0; cc < C_IN; cc++) t[cc] = 0.f;
        }
    }

    bool pr[5];
#pragma unroll
    for (int r = 0; r < 5; r++) {
        int off = 1 << r;
        int ku = __shfl_up_sync(0xffffffffu, key, off);
        pr[r] = (lane >= off) && (ku == key);
    }
#pragma unroll
    for (int r = 0; r < 5; r++) {
        int off = 1 << r;
        bool p = pr[r];
#pragma unroll
        for (int cc = 0; cc < C_IN; cc++) {
            float u = __shfl_up_sync(0xffffffffu, t[cc], off);
            if (p) t[cc] += u;
        }
    }
    int kn = __shfl_down_sync(0xffffffffu, key, 1);
    bool tail = (lane == 31) || (kn != key);
    if (valid && tail) {
        float* tp = Tagg + (size_t)dstL * TSTR;
#pragma unroll
        for (int cc = 0; cc < C_IN; cc++) atomicAdd(tp + cc, t[cc]);
    }
}

// ---------------------------------------------------------------------------
// Host-side layer driver
// ---------------------------------------------------------------------------
template <int C_IN, int C_OUT, bool RELU_IN>
static void run_layer(const float* xin,
                      const float* const* W,   // W1,b1,Wm1,bm1,Wm2,bm2,W2,b2
                      const int* ssrc, const int* sdst, const float2* sw,
                      float* Abuf, __half* Bbuf, float* Tbuf, const int* cnt,
                      const int* xmax_in, int* xmax_out,
                      float* xout,
                      int N, int E) {
    constexpr int NT = (C_IN + 7) / 8;
    int pg = N * (KP / 4);
    precomp_ab_kernel<C_IN, RELU_IN><<<(pg + 255) / 256, 256>>>(
        xin, W[2], W[3], Abuf, Bbuf, xmax_in, Tbuf, N);
    cudaFuncSetAttribute(edge_mma_kernel<C_IN, RELU_IN, NT>,
                         cudaFuncAttributeMaxDynamicSharedMemorySize, SM_TOTAL_B);
    edge_mma_kernel<C_IN, RELU_IN, NT><<<(E + 255) / 256, 256, SM_TOTAL_B>>>(
        ssrc, sdst, sw, xin, Abuf, Bbuf, W[2], W[4], W[5], xmax_in, Tbuf, E);
    node_finish_kernel<C_IN, C_OUT, RELU_IN><<<(N * C_OUT + 255) / 256, 256>>>(
        xin, W[0], W[1], W[6], W[7], Tbuf, cnt, xout, xmax_out, N);
}

extern "C" void kernel_launch(void* const* d_in, const int* in_sizes, int n_in,
                              void* d_out, int out_size) {
    const float* feat  = (const float*)d_in[0];
    const void*  edges = d_in[1];
    const float* ew    = (const float*)d_in[2];

    const float* P[24];
    for (int i = 0; i < 24; i++) P[i] = (const float*)d_in[3 + i];
    // P[0..7] = layer d, P[8..15] = layer h, P[16..23] = layer o

    int N = in_sizes[0];
    int E = in_sizes[2] / 2;

    float *x0, *x1, *A, *T;
    __half *Bhp;
    int *ssrc, *sdst, *cnt, *xm;
    float2 *sw;
    cudaGetSymbolAddress((void**)&x0,   g_x0);
    cudaGetSymbolAddress((void**)&x1,   g_x1);
    cudaGetSymbolAddress((void**)&A,    g_A);
    cudaGetSymbolAddress((void**)&Bhp,  g_Bh);
    cudaGetSymbolAddress((void**)&T,    g_T);
    cudaGetSymbolAddress((void**)&ssrc, g_ssrc);
    cudaGetSymbolAddress((void**)&sdst, g_sdst);
    cudaGetSymbolAddress((void**)&sw,   g_sw);
    cudaGetSymbolAddress((void**)&cnt,  g_cnt);
    cudaGetSymbolAddress((void**)&xm,   g_xmaxi);

    // Preprocessing: dtype detect + counting sort by dst (parallel scan)
    int nb = (N + 1023) / 1024;
    detect_edges_kernel<<<1, 32>>>((const long long*)edges);
    zero_hist_kernel<<<(N + 255) / 256, 256>>>(N);
    hist_kernel<<<(E + 255) / 256, 256>>>(edges, E);
    scan1_kernel<<<nb, 1024>>>(N);
    scan2_kernel<<<1, 32>>>(nb);
    scan3_kernel<<<nb, 1024>>>(N);
    scatter_kernel<<<(E + 255) / 256, 256>>>(edges, ew, E);

    // d layer (C_IN=1): same factorized mma path, fixed scale bs=1 (xm[7]=256.0)
    run_layer<1, 30, false>(feat, P + 0, ssrc, sdst, sw, A, Bhp, T, cnt,
                            xm + 7, xm + 0, x0, N, E);

    // hidden layers (shared weights) + output layer
    run_layer<30, 30, true>(x0, P + 8,  ssrc, sdst, sw, A, Bhp, T, cnt, xm + 0, xm + 1, x1, N, E);
    run_layer<30, 30, true>(x1, P + 8,  ssrc, sdst, sw, A, Bhp, T, cnt, xm + 1, xm + 2, x0, N, E);
    run_layer<30, 30, true>(x0, P + 8,  ssrc, sdst, sw, A, Bhp, T, cnt, xm + 2, xm + 3, x1, N, E);
    run_layer<30, 1, true>(x1,  P + 16, ssrc, sdst, sw, A, Bhp, T, cnt, xm + 3, nullptr,
                           (float*)d_out, N, E);
}

// round 14
// speedup vs baseline: 1.0801x; 1.0801x over previous
#include <cuda_runtime.h>
#include <cuda_fp16.h>
#include <cstdint>

#define NN      50000
#define NE      800000
#define NMSG    200
#define KP      208           // padded k (13 tiles of 16); A' fp32 & B fp16 row stride
#define TSTR    32            // Tagg row stride (floats)
#define W2KP    216           // Wm2T shared k-stride (halves), bank-clean
#define HSTR    24            // h-tile row stride (halves) = 48B, bank-clean
#define CSTR    36            // C staging row stride (floats)

// ---------------------------------------------------------------------------
// Static device scratch
// ---------------------------------------------------------------------------
__device__ __align__(16) float  g_x0[NN * 30];
__device__ __align__(16) float  g_x1[NN * 30];
__device__ __align__(16) float  g_A [NN * KP];    // A' = (x@Wm1a + bm1) * bs, fp32
__device__ __align__(16) __half g_Bh[NN * KP];    // B  = (x@Wm1b) * bs, fp16
__device__ __align__(16) float  g_T [NN * TSTR];
__device__ int g_is64;
__device__ int g_cnt[NN];
__device__ int g_ofs[NN];
__device__ int g_bsum[64];
__device__ int g_xmaxi[8];     // per-layer max(relu(x)) as float bits (nonneg)
__device__ int g_ssrc[NE];
__device__ int g_sdst[NE];
__device__ __align__(8) float2 g_sw[NE];

// ---------------------------------------------------------------------------
// mma.m16n8k16 f16 x f16 -> f32
// ---------------------------------------------------------------------------
__device__ __forceinline__ void mma16816(float* c,
                                         unsigned a0, unsigned a1, unsigned a2, unsigned a3,
                                         unsigned b0, unsigned b1) {
    asm volatile(
        "mma.sync.aligned.m16n8k16.row.col.f32.f16.f16.f32 "
        "{%0,%1,%2,%3}, {%4,%5,%6,%7}, {%8,%9}, {%0,%1,%2,%3};"
        : "+f"(c[0]), "+f"(c[1]), "+f"(c[2]), "+f"(c[3])
        : "r"(a0), "r"(a1), "r"(a2), "r"(a3), "r"(b0), "r"(b1));
}

// ---------------------------------------------------------------------------
// Edge dtype detection
// ---------------------------------------------------------------------------
__global__ void detect_edges_kernel(const long long* __restrict__ e64) {
    if (threadIdx.x == 0 && blockIdx.x == 0) {
        int ok = 1;
        for (int i = 0; i < 16; i++) {
            long long v = e64[i];
            if (v < 0 || v >= NN) ok = 0;
        }
        g_is64 = ok;
    }
}
__device__ __forceinline__ int load_idx(const void* edges, long long pos, bool is64) {
    if (is64) return (int)((const long long*)edges)[pos];
    return ((const int*)edges)[pos];
}

// ---------------------------------------------------------------------------
// Counting sort by dst (parallel scan)
// ---------------------------------------------------------------------------
__global__ void zero_hist_kernel(int N) {
    int i = blockIdx.x * blockDim.x + threadIdx.x;
    if (i < N) g_cnt[i] = 0;
    if (i < 8) g_xmaxi[i] = 0;
}
__global__ void hist_kernel(const void* __restrict__ edges, int E) {
    int e = blockIdx.x * blockDim.x + threadIdx.x;
    if (e >= E) return;
    bool is64 = (g_is64 != 0);
    atomicAdd(&g_cnt[load_idx(edges, (long long)E + e, is64)], 1);
}
__global__ void scan1_kernel(int N) {
    __shared__ int s[1024];
    int i = blockIdx.x * 1024 + threadIdx.x;
    int v = (i < N) ? g_cnt[i] : 0;
    s[threadIdx.x] = v;
    __syncthreads();
    for (int off = 1; off < 1024; off <<= 1) {
        int t = (threadIdx.x >= (unsigned)off) ? s[threadIdx.x - off] : 0;
        __syncthreads();
        s[threadIdx.x] += t;
        __syncthreads();
    }
    if (i < N) g_ofs[i] = s[threadIdx.x] - v;
    if (threadIdx.x == 1023) g_bsum[blockIdx.x] = s[1023];
}
__global__ void scan2_kernel(int nb) {
    if (threadIdx.x == 0 && blockIdx.x == 0) {
        int acc = 0;
        for (int b = 0; b < nb; b++) { int t = g_bsum[b]; g_bsum[b] = acc; acc += t; }
    }
}
__global__ void scan3_kernel(int N) {
    int i = blockIdx.x * 1024 + threadIdx.x;
    if (i < N) g_ofs[i] += g_bsum[blockIdx.x];
}
__global__ void scatter_kernel(const void* __restrict__ edges,
                               const float* __restrict__ ea, int E) {
    int e = blockIdx.x * blockDim.x + threadIdx.x;
    if (e >= E) return;
    bool is64 = (g_is64 != 0);
    int src = load_idx(edges, e, is64);
    int dst = load_idx(edges, (long long)E + e, is64);
    int p = atomicAdd(&g_ofs[dst], 1);
    g_ssrc[p] = src;
    g_sdst[p] = dst;
    g_sw[p]   = ((const float2*)ea)[e];
}

__global__ void zeroT_kernel(float* __restrict__ T, int n) {
    int i = blockIdx.x * blockDim.x + threadIdx.x;
    if (i < n) T[i] = 0.f;
}

// ---------------------------------------------------------------------------
// Per-node precompute, vectorized (4 k's per thread), PRE-SCALED by bs:
//   A'[n,k] = (relu?(x)·Wm1[0:C,k] + bm1[k]) * bs   (fp32)
//   B [n,k] = (relu?(x)·Wm1[C:2C,k]) * bs           (fp16)
// k >= 200 zero-padded. Also zeroes Tagg.
// ---------------------------------------------------------------------------
template <int C_IN, bool RELU_IN>
__global__ void precomp_ab_kernel(const float* __restrict__ x,
                                  const float* __restrict__ Wm1,
                                  const float* __restrict__ bm1,
                                  float* __restrict__ Ap,
                                  __half* __restrict__ Bh,
                                  const int* __restrict__ xmaxi,
                                  float* __restrict__ Tagg,
                                  int N) {
    int idx = blockIdx.x * blockDim.x + threadIdx.x;
    if (idx < N * TSTR) Tagg[idx] = 0.f;
    if (idx >= N * (KP / 4)) return;
    int n  = idx / (KP / 4);
    int kq = idx - n * (KP / 4);

    if (kq >= NMSG / 4) {   // pad region k in [200,208)
        ((float4*)(Ap + (size_t)n * KP))[kq] = make_float4(0.f, 0.f, 0.f, 0.f);
        __half2 z = __floats2half2_rn(0.f, 0.f);
        __half2* bp = (__half2*)(Bh + (size_t)n * KP + kq * 4);
        bp[0] = z; bp[1] = z;
        return;
    }

    float xmax = __int_as_float(*xmaxi);
    float bs = (xmax > 0.f) ? 256.f / xmax : 1.f;

    float4 a = ((const float4*)bm1)[kq];
    float4 b = make_float4(0.f, 0.f, 0.f, 0.f);
#pragma unroll
    for (int c = 0; c < C_IN; c++) {
        float xv = x[(size_t)n * C_IN + c];
        if (RELU_IN) xv = fmaxf(xv, 0.f);
        float4 wa = ((const float4*)(Wm1 + c * NMSG))[kq];
        float4 wb = ((const float4*)(Wm1 + (C_IN + c) * NMSG))[kq];
        a.x = fmaf(xv, wa.x, a.x); a.y = fmaf(xv, wa.y, a.y);
        a.z = fmaf(xv, wa.z, a.z); a.w = fmaf(xv, wa.w, a.w);
        b.x = fmaf(xv, wb.x, b.x); b.y = fmaf(xv, wb.y, b.y);
        b.z = fmaf(xv, wb.z, b.z); b.w = fmaf(xv, wb.w, b.w);
    }
    a.x *= bs; a.y *= bs; a.z *= bs; a.w *= bs;
    ((float4*)(Ap + (size_t)n * KP))[kq] = a;
    __half2 b01 = __floats2half2_rn(b.x * bs, b.y * bs);
    __half2 b23 = __floats2half2_rn(b.z * bs, b.w * bs);
    __half2* bp = (__half2*)(Bh + (size_t)n * KP + kq * 4);
    bp[0] = b01; bp[1] = b23;
}

// ---------------------------------------------------------------------------
// Node finish: out = b1 + deg*b2 + x@W1 + Tagg@W2; also records max(relu(out))
// ---------------------------------------------------------------------------
template <int C_IN, int C_OUT, bool RELU_IN>
__global__ void node_finish_kernel(const float* __restrict__ x,
                                   const float* __restrict__ W1,
                                   const float* __restrict__ b1,
                                   const float* __restrict__ W2,
                                   const float* __restrict__ b2,
                                   const float* __restrict__ Tagg,
                                   const int* __restrict__ cnt,
                                   float* __restrict__ out,
                                   int* __restrict__ xmax_out,   // nullable
                                   int N) {
    int idx = blockIdx.x * blockDim.x + threadIdx.x;
    float v = 0.f;
    bool inb = (idx < N * C_OUT);
    if (inb) {
        int n  = idx / C_OUT;
        int co = idx - n * C_OUT;
        v = b1[co] + (float)cnt[n] * b2[co];
#pragma unroll
        for (int c = 0; c < C_IN; c++) {
            float xv = x[(size_t)n * C_IN + c];
            if (RELU_IN) xv = fmaxf(xv, 0.f);
            v = fmaf(xv, W1[c * C_OUT + co], v);
            v = fmaf(Tagg[(size_t)n * TSTR + c], W2[c * C_OUT + co], v);
        }
        out[idx] = v;
    }
    if (xmax_out != nullptr) {
        float lv = inb ? fmaxf(v, 0.f) : 0.f;
#pragma unroll
        for (int off = 16; off > 0; off >>= 1)
            lv = fmaxf(lv, __shfl_xor_sync(0xffffffffu, lv, off));
        __shared__ float wmax[8];
        int lane = threadIdx.x & 31, warp = threadIdx.x >> 5;
        if (lane == 0) wmax[warp] = lv;
        __syncthreads();
        if (threadIdx.x == 0) {
            float bm = wmax[0];
#pragma unroll
            for (int i = 1; i < 8; i++) bm = fmaxf(bm, wmax[i]);
            atomicMax(xmax_out, __float_as_int(bm));
        }
    }
}

// ---------------------------------------------------------------------------
// d-layer edge kernel (C_IN=1): scalar t, segmented-scan aggregation
// ---------------------------------------------------------------------------
__global__ void __launch_bounds__(256)
edge_d_kernel(const int* __restrict__ srcArr,
              const int* __restrict__ dstArr,
              const float2* __restrict__ wArr,
              const float* __restrict__ x,
              const float* __restrict__ Wm1,
              const float* __restrict__ bm1,
              const float* __restrict__ Wm2,
              const float* __restrict__ bm2,
              float* __restrict__ Tagg,
              int E) {
    __shared__ __align__(16) float sW0[NMSG], sW1[NMSG], sE0[NMSG], sE1[NMSG];
    __shared__ __align__(16) float sB1[NMSG], sM2[NMSG];
    __shared__ float sbm2s;

    const int tid = threadIdx.x;
    for (int i = tid; i < NMSG; i += 256) {
        sW0[i] = Wm1[0 * NMSG + i];
        sW1[i] = Wm1[1 * NMSG + i];
        sE0[i] = Wm1[2 * NMSG + i];
        sE1[i] = Wm1[3 * NMSG + i];
        sB1[i] = bm1[i];
        sM2[i] = Wm2[i];
    }
    if (tid == 0) sbm2s = bm2[0];
    __syncthreads();

    const int e = blockIdx.x * 256 + tid;
    const bool valid = (e < E);
    const int lane = tid & 31;

    int src = 0, dstL = 0, key = -1;
    float2 w = make_float2(0.f, 0.f);
    if (valid) {
        src  = srcArr[e];
        dstL = dstArr[e];
        key  = dstL;
        w    = wArr[e];
    }
    const float xi = x[dstL];
    const float xj = x[src];

    float m = 0.f;
#pragma unroll 2
    for (int g = 0; g < NMSG / 4; g++) {
        float4 w0 = ((const float4*)sW0)[g];
        float4 w1 = ((const float4*)sW1)[g];
        float4 e0 = ((const float4*)sE0)[g];
        float4 e1 = ((const float4*)sE1)[g];
        float4 bb = ((const float4*)sB1)[g];
        float4 m2 = ((const float4*)sM2)[g];
        float h0 = fmaxf(fmaf(xi, w0.x, fmaf(xj, w1.x, fmaf(w.x, e0.x, fmaf(w.y, e1.x, bb.x)))), 0.f);
        float h1 = fmaxf(fmaf(xi, w0.y, fmaf(xj, w1.y, fmaf(w.x, e0.y, fmaf(w.y, e1.y, bb.y)))), 0.f);
        float h2 = fmaxf(fmaf(xi, w0.z, fmaf(xj, w1.z, fmaf(w.x, e0.z, fmaf(w.y, e1.z, bb.z)))), 0.f);
        float h3 = fmaxf(fmaf(xi, w0.w, fmaf(xj, w1.w, fmaf(w.x, e0.w, fmaf(w.y, e1.w, bb.w)))), 0.f);
        m = fmaf(h0, m2.x, fmaf(h1, m2.y, fmaf(h2, m2.z, fmaf(h3, m2.w, m))));
    }

    float t = valid ? (m + sbm2s) * (xi - xj) : 0.f;

#pragma unroll
    for (int r = 0; r < 5; r++) {
        int off = 1 << r;
        int ku = __shfl_up_sync(0xffffffffu, key, off);
        float tu = __shfl_up_sync(0xffffffffu, t, off);
        if (lane >= off && ku == key) t += tu;
    }
    int kn = __shfl_down_sync(0xffffffffu, key, 1);
    bool tail = (lane == 31) || (kn != key);
    if (valid && tail) atomicAdd(Tagg + (size_t)dstL * TSTR, t);
}

// ---------------------------------------------------------------------------
// Hidden/output edge kernel (C_IN=30) — TENSOR CORE GEMV, split-precision,
// with one-tile B prefetch pipeline (hides random-src L2 latency).
// ---------------------------------------------------------------------------
#define SM_WE_B    0
#define SM_W2H_B   (416 * 4)                       // 1664
#define SM_W2L_B   (SM_W2H_B + 32 * W2KP * 2)      // 15488
#define SM_BM2_B   (SM_W2L_B + 32 * W2KP * 2)      // 29312
#define SM_WARP_B  (SM_BM2_B + 128)                // 29440
#define SM_TOTAL_B (SM_WARP_B + 8 * 32 * CSTR * 4) // 66304

template <int C_IN, bool RELU_IN>
__global__ void __launch_bounds__(256)
edge_mma_kernel(const int* __restrict__ srcArr,
                const int* __restrict__ dstArr,
                const float2* __restrict__ wArr,
                const float* __restrict__ x,
                const float* __restrict__ Ap,
                const __half* __restrict__ Bh,
                const float* __restrict__ Wm1,
                const float* __restrict__ Wm2,
                const float* __restrict__ bm2,
                const int* __restrict__ xmaxi,
                float* __restrict__ Tagg,
                int E) {
    extern __shared__ char smem[];
    float*  sWE  = (float*)(smem + SM_WE_B);
    __half* sW2H = (__half*)(smem + SM_W2H_B);
    __half* sW2L = (__half*)(smem + SM_W2L_B);
    float*  sbm2 = (float*)(smem + SM_BM2_B);

    const int tid = threadIdx.x;
    for (int i = tid; i < 2 * KP; i += 256) {
        int row = i / KP, k = i - row * KP;
        sWE[i] = (k < NMSG) ? Wm1[2 * C_IN * NMSG + row * NMSG + k] : 0.f;
    }
    for (int i = tid; i < 32 * W2KP; i += 256) {
        int n = i / W2KP, k = i - n * W2KP;
        float v = (n < C_IN && k < NMSG) ? Wm2[k * C_IN + n] : 0.f;
        __half hi = __float2half_rn(v);
        sW2H[i] = hi;
        sW2L[i] = __float2half_rn(v - __half2float(hi));
    }
    if (tid < 32) sbm2[tid] = (tid < C_IN) ? bm2[tid] : 0.f;
    __syncthreads();

    const int lane = tid & 31;
    const int warp = tid >> 5;
    const int gq   = lane >> 2;
    const int tg   = lane & 3;
    float*  wb   = (float*)(smem + SM_WARP_B) + warp * (32 * CSTR);
    __half* htH  = (__half*)wb;
    __half* htL  = htH + 32 * HSTR;

    const float xmax   = __int_as_float(*xmaxi);
    const float inv_bs = (xmax > 0.f) ? xmax * (1.f / 256.f) : 1.f;
    const float bs     = (xmax > 0.f) ? 256.f / xmax : 1.f;

    const int e = blockIdx.x * 256 + warp * 32 + lane;
    const bool valid = (e < E);
    int src = 0, dstL = 0, key = -1;
    float2 w = make_float2(0.f, 0.f);
    if (valid) {
        src  = srcArr[e];
        dstL = dstArr[e];
        key  = dstL;
        w    = wArr[e];
    }
    const float wxs = w.x * bs;
    const float wys = w.y * bs;

    const float* Arow = Ap + (size_t)dstL * KP;
    const uint4* B8   = (const uint4*)(Bh + (size_t)src * KP);

    float c[8][4];
#pragma unroll
    for (int i = 0; i < 8; i++)
#pragma unroll
        for (int j = 0; j < 4; j++) c[i][j] = 0.f;

    // B prefetch pipeline (src is random -> L2 latency; hide behind compute)
    uint4 pb0 = B8[0];
    uint4 pb1 = B8[1];

#pragma unroll 1
    for (int kt = 0; kt < KP / 16; kt++) {        // 13 tiles
        const int k0 = kt * 16;
        uint4 cb0 = pb0, cb1 = pb1;
        if (kt + 1 < KP / 16) {
            pb0 = B8[(kt + 1) * 2];
            pb1 = B8[(kt + 1) * 2 + 1];
        }

        __align__(16) __half2 hhH[8];
        __align__(16) __half2 hhL[8];
#pragma unroll
        for (int hc = 0; hc < 2; hc++) {
            const int kk = k0 + hc * 8;
            float4 a0 = ((const float4*)(Arow + kk))[0];
            float4 a1 = ((const float4*)(Arow + kk))[1];
            uint4  bv = (hc == 0) ? cb0 : cb1;
            float4 u00 = ((const float4*)(sWE + kk))[0];
            float4 u01 = ((const float4*)(sWE + kk))[1];
            float4 u10 = ((const float4*)(sWE + KP + kk))[0];
            float4 u11 = ((const float4*)(sWE + KP + kk))[1];
            float2 b0 = __half22float2(*(const __half2*)&bv.x);
            float2 b1 = __half22float2(*(const __half2*)&bv.y);
            float2 b2 = __half22float2(*(const __half2*)&bv.z);
            float2 b3 = __half22float2(*(const __half2*)&bv.w);
            float h[8];
            h[0] = fmaxf(fmaf(wxs, u00.x, fmaf(wys, u10.x, a0.x + b0.x)), 0.f);
            h[1] = fmaxf(fmaf(wxs, u00.y, fmaf(wys, u10.y, a0.y + b0.y)), 0.f);
            h[2] = fmaxf(fmaf(wxs, u00.z, fmaf(wys, u10.z, a0.z + b1.x)), 0.f);
            h[3] = fmaxf(fmaf(wxs, u00.w, fmaf(wys, u10.w, a0.w + b1.y)), 0.f);
            h[4] = fmaxf(fmaf(wxs, u01.x, fmaf(wys, u11.x, a1.x + b2.x)), 0.f);
            h[5] = fmaxf(fmaf(wxs, u01.y, fmaf(wys, u11.y, a1.y + b2.y)), 0.f);
            h[6] = fmaxf(fmaf(wxs, u01.z, fmaf(wys, u11.z, a1.z + b3.x)), 0.f);
            h[7] = fmaxf(fmaf(wxs, u01.w, fmaf(wys, u11.w, a1.w + b3.y)), 0.f);
#pragma unroll
            for (int p = 0; p < 4; p++) {
                __half2 hi = __floats2half2_rn(h[2 * p], h[2 * p + 1]);
                float2 hif = __half22float2(hi);
                __half2 lo = __floats2half2_rn(h[2 * p] - hif.x, h[2 * p + 1] - hif.y);
                hhH[hc * 4 + p] = hi;
                hhL[hc * 4 + p] = lo;
            }
        }
        {
            uint4* hwH = (uint4*)(htH + lane * HSTR);
            hwH[0] = *(const uint4*)&hhH[0];
            hwH[1] = *(const uint4*)&hhH[4];
            uint4* hwL = (uint4*)(htL + lane * HSTR);
            hwL[0] = *(const uint4*)&hhL[0];
            hwL[1] = *(const uint4*)&hhL[4];
        }
        __syncwarp();

        unsigned bfH[4][2], bfL[4][2];
#pragma unroll
        for (int nt = 0; nt < 4; nt++) {
            const __half* wpH = sW2H + (nt * 8 + gq) * W2KP + k0 + 2 * tg;
            bfH[nt][0] = *(const unsigned*)wpH;
            bfH[nt][1] = *(const unsigned*)(wpH + 8);
            const __half* wpL = sW2L + (nt * 8 + gq) * W2KP + k0 + 2 * tg;
            bfL[nt][0] = *(const unsigned*)wpL;
            bfL[nt][1] = *(const unsigned*)(wpL + 8);
        }
#pragma unroll
        for (int mt = 0; mt < 2; mt++) {
            const __half* hbH = htH + mt * 16 * HSTR;
            unsigned aH0 = *(const unsigned*)(hbH + gq * HSTR + 2 * tg);
            unsigned aH1 = *(const unsigned*)(hbH + (gq + 8) * HSTR + 2 * tg);
            unsigned aH2 = *(const unsigned*)(hbH + gq * HSTR + 2 * tg + 8);
            unsigned aH3 = *(const unsigned*)(hbH + (gq + 8) * HSTR + 2 * tg + 8);
            const __half* hbL = htL + mt * 16 * HSTR;
            unsigned aL0 = *(const unsigned*)(hbL + gq * HSTR + 2 * tg);
            unsigned aL1 = *(const unsigned*)(hbL + (gq + 8) * HSTR + 2 * tg);
            unsigned aL2 = *(const unsigned*)(hbL + gq * HSTR + 2 * tg + 8);
            unsigned aL3 = *(const unsigned*)(hbL + (gq + 8) * HSTR + 2 * tg + 8);
#pragma unroll
            for (int nt = 0; nt < 4; nt++) {
                mma16816(c[mt * 4 + nt], aH0, aH1, aH2, aH3, bfH[nt][0], bfH[nt][1]);
                mma16816(c[mt * 4 + nt], aH0, aH1, aH2, aH3, bfL[nt][0], bfL[nt][1]);
                mma16816(c[mt * 4 + nt], aL0, aL1, aL2, aL3, bfH[nt][0], bfH[nt][1]);
            }
        }
        __syncwarp();
    }

    // Stage C frags to smem: row = edge-in-warp, col = n
#pragma unroll
    for (int mt = 0; mt < 2; mt++)
#pragma unroll
        for (int nt = 0; nt < 4; nt++) {
            float* p = wb + (mt * 16 + gq) * CSTR + nt * 8 + 2 * tg;
            p[0] = c[mt * 4 + nt][0];
            p[1] = c[mt * 4 + nt][1];
            p[8 * CSTR + 0] = c[mt * 4 + nt][2];
            p[8 * CSTR + 1] = c[mt * 4 + nt][3];
        }
    __syncwarp();

    // Per-edge m, t, segmented scan, tail atomics
    float t[C_IN];
    {
        const float* mrow = wb + lane * CSTR;
        const float2* xd2 = (const float2*)(x + (size_t)dstL * C_IN);
        const float2* xs2 = (const float2*)(x + (size_t)src  * C_IN);
#pragma unroll
        for (int p = 0; p < C_IN / 2; p++) {
            float2 xi = xd2[p];
            float2 xj = xs2[p];
            if (RELU_IN) {
                xi.x = fmaxf(xi.x, 0.f); xi.y = fmaxf(xi.y, 0.f);
                xj.x = fmaxf(xj.x, 0.f); xj.y = fmaxf(xj.y, 0.f);
            }
            t[2 * p]     = fmaf(mrow[2 * p],     inv_bs, sbm2[2 * p])     * (xi.x - xj.x);
            t[2 * p + 1] = fmaf(mrow[2 * p + 1], inv_bs, sbm2[2 * p + 1]) * (xi.y - xj.y);
        }
        if (!valid) {
#pragma unroll
            for (int cc = 0; cc < C_IN; cc++) t[cc] = 0.f;
        }
    }

    bool pr[5];
#pragma unroll
    for (int r = 0; r < 5; r++) {
        int off = 1 << r;
        int ku = __shfl_up_sync(0xffffffffu, key, off);
        pr[r] = (lane >= off) && (ku == key);
    }
#pragma unroll
    for (int r = 0; r < 5; r++) {
        int off = 1 << r;
        bool p = pr[r];
#pragma unroll
        for (int cc = 0; cc < C_IN; cc++) {
            float u = __shfl_up_sync(0xffffffffu, t[cc], off);
            if (p) t[cc] += u;
        }
    }
    int kn = __shfl_down_sync(0xffffffffu, key, 1);
    bool tail = (lane == 31) || (kn != key);
    if (valid && tail) {
        float* tp = Tagg + (size_t)dstL * TSTR;
#pragma unroll
        for (int cc = 0; cc < C_IN; cc++) atomicAdd(tp + cc, t[cc]);
    }
}

// ---------------------------------------------------------------------------
// Host-side layer driver (C_IN=30 layers)
// ---------------------------------------------------------------------------
template <int C_IN, int C_OUT, bool RELU_IN>
static void run_layer(const float* xin,
                      const float* const* W,   // W1,b1,Wm1,bm1,Wm2,bm2,W2,b2
                      const int* ssrc, const int* sdst, const float2* sw,
                      float* Abuf, __half* Bbuf, float* Tbuf, const int* cnt,
                      const int* xmax_in, int* xmax_out,
                      float* xout,
                      int N, int E) {
    int pg = N * (KP / 4);
    precomp_ab_kernel<C_IN, RELU_IN><<<(pg + 255) / 256, 256>>>(
        xin, W[2], W[3], Abuf, Bbuf, xmax_in, Tbuf, N);
    cudaFuncSetAttribute(edge_mma_kernel<C_IN, RELU_IN>,
                         cudaFuncAttributeMaxDynamicSharedMemorySize, SM_TOTAL_B);
    edge_mma_kernel<C_IN, RELU_IN><<<(E + 255) / 256, 256, SM_TOTAL_B>>>(
        ssrc, sdst, sw, xin, Abuf, Bbuf, W[2], W[4], W[5], xmax_in, Tbuf, E);
    node_finish_kernel<C_IN, C_OUT, RELU_IN><<<(N * C_OUT + 255) / 256, 256>>>(
        xin, W[0], W[1], W[6], W[7], Tbuf, cnt, xout, xmax_out, N);
}

extern "C" void kernel_launch(void* const* d_in, const int* in_sizes, int n_in,
                              void* d_out, int out_size) {
    const float* feat  = (const float*)d_in[0];
    const void*  edges = d_in[1];
    const float* ew    = (const float*)d_in[2];

    const float* P[24];
    for (int i = 0; i < 24; i++) P[i] = (const float*)d_in[3 + i];
    // P[0..7] = layer d, P[8..15] = layer h, P[16..23] = layer o

    int N = in_sizes[0];
    int E = in_sizes[2] / 2;

    float *x0, *x1, *A, *T;
    __half *Bhp;
    int *ssrc, *sdst, *cnt, *xm;
    float2 *sw;
    cudaGetSymbolAddress((void**)&x0,   g_x0);
    cudaGetSymbolAddress((void**)&x1,   g_x1);
    cudaGetSymbolAddress((void**)&A,    g_A);
    cudaGetSymbolAddress((void**)&Bhp,  g_Bh);
    cudaGetSymbolAddress((void**)&T,    g_T);
    cudaGetSymbolAddress((void**)&ssrc, g_ssrc);
    cudaGetSymbolAddress((void**)&sdst, g_sdst);
    cudaGetSymbolAddress((void**)&sw,   g_sw);
    cudaGetSymbolAddress((void**)&cnt,  g_cnt);
    cudaGetSymbolAddress((void**)&xm,   g_xmaxi);

    // Preprocessing: dtype detect + counting sort by dst (parallel scan)
    int nb = (N + 1023) / 1024;
    detect_edges_kernel<<<1, 32>>>((const long long*)edges);
    zero_hist_kernel<<<(N + 255) / 256, 256>>>(N);
    hist_kernel<<<(E + 255) / 256, 256>>>(edges, E);
    scan1_kernel<<<nb, 1024>>>(N);
    scan2_kernel<<<1, 32>>>(nb);
    scan3_kernel<<<nb, 1024>>>(N);
    scatter_kernel<<<(E + 255) / 256, 256>>>(edges, ew, E);

    // d layer: scalar-x edge kernel; node_finish records xmax of relu(x0) -> xm[0]
    zeroT_kernel<<<(N * TSTR + 255) / 256, 256>>>(T, N * TSTR);
    edge_d_kernel<<<(E + 255) / 256, 256>>>(
        ssrc, sdst, sw, feat, P[2], P[3], P[4], P[5], T, E);
    node_finish_kernel<1, 30, false><<<(N * 30 + 255) / 256, 256>>>(
        feat, P[0], P[1], P[6], P[7], T, cnt, x0, xm + 0, N);

    // hidden layers (shared weights) + output layer
    run_layer<30, 30, true>(x0, P + 8,  ssrc, sdst, sw, A, Bhp, T, cnt, xm + 0, xm + 1, x1, N, E);
    run_layer<30, 30, true>(x1, P + 8,  ssrc, sdst, sw, A, Bhp, T, cnt, xm + 1, xm + 2, x0, N, E);
    run_layer<30, 30, true>(x0, P + 8,  ssrc, sdst, sw, A, Bhp, T, cnt, xm + 2, xm + 3, x1, N, E);
    run_layer<30, 1, true>(x1,  P + 16, ssrc, sdst, sw, A, Bhp, T, cnt, xm + 3, nullptr,
                           (float*)d_out, N, E);
}